// round 15
// baseline (speedup 1.0000x reference)
#include <cuda_runtime.h>

#define NPTS  8192
#define TPB   512
#define PPT   16           // points per thread (512*16 = 8192 exactly)
#define NC    10
#define NCELL 100
#define GRIDB 148          // pad grid to >=148
#define CAP   192          // own-cell capacity (mean 82)
#define NOWN  (CAP + 8)
#define NSH   (4 * CAP)    // shell capacity (mean ~330)
#define MIN_DISTF 0.1f

// scratch (module-load zero-init; last block resets g_cnt each launch)
__device__ float g_pen[NCELL];
__device__ float g_mse[NCELL];
__device__ int   g_cnt = 0;

__device__ __forceinline__ float rsq(float x) {
    float r;
    asm("rsqrt.approx.f32 %0, %1;" : "=f"(r) : "f"(x));
    return r;
}

// branchless pair: d2<=0 or d>=0.1 (incl. 1e9 sentinels) contribute exactly 0
#define PAIR(xi, yi, xj, yj, acc)                          \
    {                                                      \
        float dx_ = (xi) - (xj), dy_ = (yi) - (yj);        \
        float d2_ = fmaf(dx_, dx_, dy_ * dy_);             \
        float r_  = rsq(d2_);                              \
        float m_  = fmaxf(fmaf(d2_, -r_, MIN_DISTF), 0.f); \
        (acc) = fmaf(m_, m_, (acc));                       \
    }

__global__ void __launch_bounds__(TPB) k_all(const float2* __restrict__ pts,
                                             const float2* __restrict__ tg,
                                             float* __restrict__ out) {
    __shared__ __align__(16) float sOx[NOWN];
    __shared__ __align__(16) float sOy[NOWN];
    __shared__ __align__(16) float sNx[NSH];
    __shared__ __align__(16) float sNy[NSH];
    __shared__ int   smW[TPB / 32];
    __shared__ int   totals;             // packed (own | shell<<16)
    __shared__ float smP[TPB / 32];
    __shared__ float smM[TPB / 32];
    __shared__ int   lastFlag;

    const int b = blockIdx.x;
    if (b >= NCELL) return;

    const int tid  = threadIdx.x;
    const int cx   = b % NC, cy = b / NC;
    const int lane = tid & 31, w = tid >> 5;
    const int c0   = cy * 16 + cx;       // packed cell id (stride 16)

    // ---- issue ALL global loads up front (MSE pair + 8x LDG.128) ----
    const bool hasM = tid < 82 && (b * 82 + tid) < NPTS;
    float2 pm = {0.f, 0.f}, tm = {0.f, 0.f};
    if (hasM) {
        int i = b * 82 + tid;
        pm = pts[i];
        tm = tg[i];
    }
    const float4* p4 = reinterpret_cast<const float4*>(pts);
    float4 r[PPT / 2];
#pragma unroll
    for (int t = 0; t < PPT / 2; t++) r[t] = p4[tid + t * TPB];

    // ---- classify in registers (packed cell-id diff) ----
    unsigned ownM = 0, shM = 0;
    int co = 0, cs = 0;
#pragma unroll
    for (int t = 0; t < PPT; t++) {
        float qx = (t & 1) ? r[t >> 1].z : r[t >> 1].x;
        float qy = (t & 1) ? r[t >> 1].w : r[t >> 1].y;
        int qcx = (int)(qx * 10.f); qcx = qcx > 9 ? 9 : qcx;
        int qcy = (int)(qy * 10.f); qcy = qcy > 9 ? 9 : qcy;
        int d = qcy * 16 + qcx - c0;
        bool own   = d == 0;
        // half shell (+1,0),(-1,+1),(0,+1),(+1,+1) -> d in {1, 15, 16, 17}
        bool shell = (d == 1) | ((unsigned)(d - 15) <= 2u);
        ownM |= own   ? (1u << t) : 0u;
        shM  |= shell ? (1u << t) : 0u;
        co += own;
        cs += shell;
    }

    // ---- ONE block exclusive scan of packed (co | cs<<16) ----
    int val = co | (cs << 16);
    int inc = val;
#pragma unroll
    for (int o = 1; o < 32; o <<= 1) {
        int y = __shfl_up_sync(0xffffffffu, inc, o);
        if (lane >= o) inc += y;
    }
    if (lane == 31) smW[w] = inc;
    int pre = inc - val;
    __syncthreads();
    if (w == 0) {
        int t = (lane < TPB / 32) ? smW[lane] : 0;
        int ti = t;
#pragma unroll
        for (int o = 1; o < 32; o <<= 1) {
            int y = __shfl_up_sync(0xffffffffu, ti, o);
            if (lane >= o) ti += y;
        }
        if (lane < TPB / 32) smW[lane] = ti - t;
        if (lane == TPB / 32 - 1) totals = ti;
    }
    __syncthreads();
    int base = smW[w] + pre;
    int oo   = base & 0xffff;
    int ss   = base >> 16;
    const int nOt = totals & 0xffff;
    const int nNt = totals >> 16;
    const int nO  = nOt > CAP ? CAP : nOt;
    const int nN  = nNt > NSH ? NSH : nNt;
    const int nor = (nO + 3) & ~3;

    // ---- write hits at exact offsets + sentinel pad, then ONE sync ----
#pragma unroll
    for (int t = 0; t < PPT; t++) {
        if (ownM & (1u << t)) {
            if (oo < CAP) {
                sOx[oo] = (t & 1) ? r[t >> 1].z : r[t >> 1].x;
                sOy[oo] = (t & 1) ? r[t >> 1].w : r[t >> 1].y;
            }
            oo++;
        } else if (shM & (1u << t)) {
            if (ss < NSH) {
                sNx[ss] = (t & 1) ? r[t >> 1].z : r[t >> 1].x;
                sNy[ss] = (t & 1) ? r[t >> 1].w : r[t >> 1].y;
            }
            ss++;
        }
    }
    if (tid < 8) { sOx[nO + tid] = 1e9f; sOy[nO + tid] = 1e9f; }
    float mse = 0.f;
    if (hasM) {
        float dx = pm.x - tm.x, dy = pm.y - tm.y;
        mse = fmaf(dx, dx, dy * dy);
    }
    __syncthreads();

    const float4* ox4 = reinterpret_cast<const float4*>(sOx);
    const float4* oy4 = reinterpret_cast<const float4*>(sOy);
    const int     ni4 = nor >> 2;
    const int     q   = tid & 3;

    float a0 = 0.f, a1 = 0.f, a2 = 0.f, a3 = 0.f;

    // cross pairs: 4 threads per shell candidate, each owns a quarter of the
    // own tile (i4 = q, q+4, ...). All 512 threads busy; ~55 pairs/thread.
    for (int j = tid >> 2; j < nN; j += TPB / 4) {
        float xj = sNx[j], yj = sNy[j];
        for (int i4 = q; i4 < ni4; i4 += 4) {
            float4 qx = ox4[i4];
            float4 qy = oy4[i4];
            PAIR(qx.x, qy.x, xj, yj, a0);
            PAIR(qx.y, qy.y, xj, yj, a1);
            PAIR(qx.z, qy.z, xj, yj, a2);
            PAIR(qx.w, qy.w, xj, yj, a3);
        }
    }

    // self pairs: 4 threads per i-row, groups-of-4 j strided by 16
    if (tid < 4 * nO) {
        const int   i  = tid >> 2;
        const float xi = sOx[i], yi = sOy[i];
        for (int j = i + 1 + 4 * q; j < nor; j += 16) {
            PAIR(xi, yi, sOx[j + 0], sOy[j + 0], a0);
            PAIR(xi, yi, sOx[j + 1], sOy[j + 1], a1);
            PAIR(xi, yi, sOx[j + 2], sOy[j + 2], a2);
            PAIR(xi, yi, sOx[j + 3], sOy[j + 3], a3);
        }
    }

    // ---- block reduction (pen, mse) ----
    float pen = (a0 + a1) + (a2 + a3);
#pragma unroll
    for (int o = 16; o > 0; o >>= 1) {
        pen += __shfl_xor_sync(0xffffffffu, pen, o);
        mse += __shfl_xor_sync(0xffffffffu, mse, o);
    }
    if (lane == 0) { smP[w] = pen; smM[w] = mse; }
    __syncthreads();
    if (tid == 0) {
        float ps = 0.f, ms = 0.f;
#pragma unroll
        for (int x = 0; x < TPB / 32; x++) { ps += smP[x]; ms += smM[x]; }
        g_pen[b] = ps;
        g_mse[b] = ms;
        int ticket;
        asm volatile("atom.acq_rel.gpu.global.add.s32 %0, [%1], 1;"
                     : "=r"(ticket) : "l"(&g_cnt) : "memory");
        lastFlag = (ticket == NCELL - 1);
    }
    __syncthreads();

    // ---- last block: deterministic fp64 final reduction ----
    if (lastFlag && w == 0) {
        double pd = 0.0, md = 0.0;
#pragma unroll
        for (int x = 0; x < 4; x++) {
            int idx = lane + x * 32;
            if (idx < NCELL) {
                pd += (double)__ldcg(&g_pen[idx]);
                md += (double)__ldcg(&g_mse[idx]);
            }
        }
#pragma unroll
        for (int o = 16; o > 0; o >>= 1) {
            pd += __shfl_xor_sync(0xffffffffu, pd, o);
            md += __shfl_xor_sync(0xffffffffu, md, o);
        }
        if (lane == 0) {
            out[0] = (float)(md * (1.0 / (double)(NPTS * 2)) + pd);
            g_cnt  = 0;
        }
    }
}

extern "C" void kernel_launch(void* const* d_in, const int* in_sizes, int n_in,
                              void* d_out, int out_size) {
    const float2* pred = (const float2*)d_in[0];
    const float2* targ = (const float2*)d_in[1];
    k_all<<<GRIDB, TPB>>>(pred, targ, (float*)d_out);
}

// round 16
// speedup vs baseline: 1.0173x; 1.0173x over previous
#include <cuda_runtime.h>

#define NPTS  8192
#define TPB   512
#define PPT   16           // points per thread (512*16 = 8192 exactly)
#define NC    10
#define NCELL 100
#define NWB   200          // work blocks: 100 cells x 2 halves
#define GRIDB 296          // 2 blocks resident per SM; blocks >= NWB no-op
#define CAP   192          // own-cell capacity (mean 82)
#define NOWN  (CAP + 8)
#define NSH   (4 * CAP)    // shell capacity (mean ~330)
#define MIN_DISTF 0.1f

// scratch (module-load zero-init; last block resets g_cnt each launch)
__device__ float g_pen[NWB];
__device__ float g_mse[NWB];
__device__ int   g_cnt = 0;

__device__ __forceinline__ float rsq(float x) {
    float r;
    asm("rsqrt.approx.f32 %0, %1;" : "=f"(r) : "f"(x));
    return r;
}

// branchless pair: d2<=0 or d>=0.1 (incl. 1e9 sentinels) contribute exactly 0
#define PAIR(xi, yi, xj, yj, acc)                          \
    {                                                      \
        float dx_ = (xi) - (xj), dy_ = (yi) - (yj);        \
        float d2_ = fmaf(dx_, dx_, dy_ * dy_);             \
        float r_  = rsq(d2_);                              \
        float m_  = fmaxf(fmaf(d2_, -r_, MIN_DISTF), 0.f); \
        (acc) = fmaf(m_, m_, (acc));                       \
    }

__global__ void __launch_bounds__(TPB, 2) k_all(const float2* __restrict__ pts,
                                                const float2* __restrict__ tg,
                                                float* __restrict__ out) {
    __shared__ __align__(16) float sOx[NOWN];
    __shared__ __align__(16) float sOy[NOWN];
    __shared__ __align__(16) float sNx[NSH];
    __shared__ __align__(16) float sNy[NSH];
    __shared__ int   smW[TPB / 32];
    __shared__ int   totals;             // packed (own | shell<<16)
    __shared__ float smP[TPB / 32];
    __shared__ float smM[TPB / 32];
    __shared__ int   lastFlag;

    const int b = blockIdx.x;
    if (b >= NWB) return;                // padding blocks: no-op

    const int c = b >> 1;                // cell
    const int h = b & 1;                 // half (0/1)
    const int tid  = threadIdx.x;
    const int cx   = c % NC, cy = c / NC;
    const int lane = tid & 31, w = tid >> 5;
    const int c0   = cy * 16 + cx;       // packed cell id (stride 16)

    // ---- issue ALL global loads up front (MSE pair + 8x LDG.128) ----
    const bool hasM = tid < 41 && (b * 41 + tid) < NPTS;
    float2 pm = {0.f, 0.f}, tm = {0.f, 0.f};
    if (hasM) {
        int i = b * 41 + tid;
        pm = pts[i];
        tm = tg[i];
    }
    const float4* p4 = reinterpret_cast<const float4*>(pts);
    float4 r[PPT / 2];
#pragma unroll
    for (int t = 0; t < PPT / 2; t++) r[t] = p4[tid + t * TPB];

    // ---- classify in registers (packed cell-id diff) ----
    unsigned ownM = 0, shM = 0;
    int co = 0, cs = 0;
#pragma unroll
    for (int t = 0; t < PPT; t++) {
        float qx = (t & 1) ? r[t >> 1].z : r[t >> 1].x;
        float qy = (t & 1) ? r[t >> 1].w : r[t >> 1].y;
        int qcx = (int)(qx * 10.f); qcx = qcx > 9 ? 9 : qcx;
        int qcy = (int)(qy * 10.f); qcy = qcy > 9 ? 9 : qcy;
        int d = qcy * 16 + qcx - c0;
        bool own   = d == 0;
        // half shell (+1,0),(-1,+1),(0,+1),(+1,+1) -> d in {1, 15, 16, 17}
        bool shell = (d == 1) | ((unsigned)(d - 15) <= 2u);
        ownM |= own   ? (1u << t) : 0u;
        shM  |= shell ? (1u << t) : 0u;
        co += own;
        cs += shell;
    }

    // ---- ONE block exclusive scan of packed (co | cs<<16) ----
    int val = co | (cs << 16);
    int inc = val;
#pragma unroll
    for (int o = 1; o < 32; o <<= 1) {
        int y = __shfl_up_sync(0xffffffffu, inc, o);
        if (lane >= o) inc += y;
    }
    if (lane == 31) smW[w] = inc;
    int pre = inc - val;
    __syncthreads();
    if (w == 0) {
        int t = (lane < TPB / 32) ? smW[lane] : 0;
        int ti = t;
#pragma unroll
        for (int o = 1; o < 32; o <<= 1) {
            int y = __shfl_up_sync(0xffffffffu, ti, o);
            if (lane >= o) ti += y;
        }
        if (lane < TPB / 32) smW[lane] = ti - t;
        if (lane == TPB / 32 - 1) totals = ti;
    }
    __syncthreads();
    int base = smW[w] + pre;
    int oo   = base & 0xffff;
    int ss   = base >> 16;
    const int nOt = totals & 0xffff;
    const int nNt = totals >> 16;
    const int nO  = nOt > CAP ? CAP : nOt;
    const int nN  = nNt > NSH ? NSH : nNt;
    const int nor = (nO + 3) & ~3;

    // ---- write hits at exact offsets + sentinel pad, then ONE sync ----
#pragma unroll
    for (int t = 0; t < PPT; t++) {
        if (ownM & (1u << t)) {
            if (oo < CAP) {
                sOx[oo] = (t & 1) ? r[t >> 1].z : r[t >> 1].x;
                sOy[oo] = (t & 1) ? r[t >> 1].w : r[t >> 1].y;
            }
            oo++;
        } else if (shM & (1u << t)) {
            if (ss < NSH) {
                sNx[ss] = (t & 1) ? r[t >> 1].z : r[t >> 1].x;
                sNy[ss] = (t & 1) ? r[t >> 1].w : r[t >> 1].y;
            }
            ss++;
        }
    }
    if (tid < 8) { sOx[nO + tid] = 1e9f; sOy[nO + tid] = 1e9f; }
    float mse = 0.f;
    if (hasM) {
        float dx = pm.x - tm.x, dy = pm.y - tm.y;
        mse = fmaf(dx, dx, dy * dy);
    }
    __syncthreads();

    const float4* ox4 = reinterpret_cast<const float4*>(sOx);
    const float4* oy4 = reinterpret_cast<const float4*>(sOy);
    const int     ni4 = nor >> 2;
    const int     q   = tid & 3;

    float a0 = 0.f, a1 = 0.f, a2 = 0.f, a3 = 0.f;

    // cross pairs: this half takes candidates j with parity h; 4 threads per
    // candidate, each covering a quarter of the own tile.
    for (int j = 2 * (tid >> 2) + h; j < nN; j += TPB / 2) {
        float xj = sNx[j], yj = sNy[j];
        for (int i4 = q; i4 < ni4; i4 += 4) {
            float4 qx = ox4[i4];
            float4 qy = oy4[i4];
            PAIR(qx.x, qy.x, xj, yj, a0);
            PAIR(qx.y, qy.y, xj, yj, a1);
            PAIR(qx.z, qy.z, xj, yj, a2);
            PAIR(qx.w, qy.w, xj, yj, a3);
        }
    }

    // self pairs: rows i with parity h; 4 threads per row, 4-wide j groups
    {
        const int i = 2 * (tid >> 2) + h;
        if (i < nO) {
            const float xi = sOx[i], yi = sOy[i];
            for (int j = i + 1 + 4 * q; j < nor; j += 16) {
                PAIR(xi, yi, sOx[j + 0], sOy[j + 0], a0);
                PAIR(xi, yi, sOx[j + 1], sOy[j + 1], a1);
                PAIR(xi, yi, sOx[j + 2], sOy[j + 2], a2);
                PAIR(xi, yi, sOx[j + 3], sOy[j + 3], a3);
            }
        }
    }

    // ---- block reduction (pen, mse) ----
    float pen = (a0 + a1) + (a2 + a3);
#pragma unroll
    for (int o = 16; o > 0; o >>= 1) {
        pen += __shfl_xor_sync(0xffffffffu, pen, o);
        mse += __shfl_xor_sync(0xffffffffu, mse, o);
    }
    if (lane == 0) { smP[w] = pen; smM[w] = mse; }
    __syncthreads();
    if (tid == 0) {
        float ps = 0.f, ms = 0.f;
#pragma unroll
        for (int x = 0; x < TPB / 32; x++) { ps += smP[x]; ms += smM[x]; }
        g_pen[b] = ps;
        g_mse[b] = ms;
        int ticket;
        asm volatile("atom.acq_rel.gpu.global.add.s32 %0, [%1], 1;"
                     : "=r"(ticket) : "l"(&g_cnt) : "memory");
        lastFlag = (ticket == NWB - 1);
    }
    __syncthreads();

    // ---- last block: deterministic fp64 final reduction ----
    if (lastFlag && w == 0) {
        double pd = 0.0, md = 0.0;
#pragma unroll
        for (int x = 0; x < 7; x++) {
            int idx = lane + x * 32;
            if (idx < NWB) {
                pd += (double)__ldcg(&g_pen[idx]);
                md += (double)__ldcg(&g_mse[idx]);
            }
        }
#pragma unroll
        for (int o = 16; o > 0; o >>= 1) {
            pd += __shfl_xor_sync(0xffffffffu, pd, o);
            md += __shfl_xor_sync(0xffffffffu, md, o);
        }
        if (lane == 0) {
            out[0] = (float)(md * (1.0 / (double)(NPTS * 2)) + pd);
            g_cnt  = 0;
        }
    }
}

extern "C" void kernel_launch(void* const* d_in, const int* in_sizes, int n_in,
                              void* d_out, int out_size) {
    const float2* pred = (const float2*)d_in[0];
    const float2* targ = (const float2*)d_in[1];
    k_all<<<GRIDB, TPB>>>(pred, targ, (float*)d_out);
}